// round 2
// baseline (speedup 1.0000x reference)
#include <cuda_runtime.h>
#include <math.h>

#define MAXN 50000
#define MAXE 1250000
#define F 64
#define D 256

// Scratch (allocation-free): ~18 MB of __device__ globals
__device__ float g_z[MAXN * F];       // projected features z[n, f]
__device__ float g_ex[MAXE];          // edge score e, later exp(e - emax)
__device__ float g_emax[MAXN];        // per-dst segment max
__device__ float g_denom[MAXN];       // per-dst softmax denominator

__device__ __forceinline__ void atomicMaxFloat(float* addr, float val) {
    // Ordered-int encoding trick; works for mixed signs with -inf init.
    if (val >= 0.0f)
        atomicMax((int*)addr, __float_as_int(val));
    else
        atomicMin((unsigned int*)addr, (unsigned int)__float_as_int(val));
}

// K0: zero output, init emax/denom
__global__ void k_init(float* __restrict__ out, int N) {
    int i = blockIdx.x * blockDim.x + threadIdx.x;
    if (i < N * F) out[i] = 0.0f;
    if (i < N) {
        g_emax[i] = -INFINITY;
        g_denom[i] = 0.0f;
    }
}

// K1: type-gated projection z = (type? d_sim : m_sim) @ (type? W_d : W_m)
// 8 nodes per block, 64 threads (one per output feature).
// W rows read coalesced per k; x rows staged in shared.
__global__ void k_project(const float* __restrict__ d_sim,
                          const float* __restrict__ m_sim,
                          const float* __restrict__ Wd,
                          const float* __restrict__ Wm,
                          const int* __restrict__ ntype, int N) {
    __shared__ float xs[8][D];
    __shared__ int ty[8];
    int t = threadIdx.x;            // 0..63, output feature
    int base = blockIdx.x * 8;

    if (t < 8) {
        int n = base + t;
        ty[t] = (n < N) ? ntype[n] : 0;
    }
    __syncthreads();

    for (int i = t; i < 8 * D; i += 64) {
        int r = i >> 8;
        int c = i & (D - 1);
        int n = base + r;
        if (n < N) {
            const float* p = ty[r] ? d_sim : m_sim;
            xs[r][c] = p[(long)n * D + c];
        }
    }
    __syncthreads();

    int tl[8];
#pragma unroll
    for (int m = 0; m < 8; m++) tl[m] = ty[m];

    float acc[8];
#pragma unroll
    for (int m = 0; m < 8; m++) acc[m] = 0.0f;

#pragma unroll 4
    for (int k = 0; k < D; k++) {
        float wd = __ldg(Wd + k * F + t);
        float wm = __ldg(Wm + k * F + t);
#pragma unroll
        for (int m = 0; m < 8; m++) {
            float w = tl[m] ? wd : wm;
            acc[m] = fmaf(xs[m][k], w, acc[m]);
        }
    }

#pragma unroll
    for (int m = 0; m < 8; m++) {
        int n = base + m;
        if (n < N) g_z[n * F + t] = acc[m];
    }
}

// K2: edge score e = leaky_relu(<z[src], z[dst]>), atomicMax into emax[dst].
// One warp per edge; each lane handles a float2 (64 features total).
__global__ void k_edge(const int* __restrict__ src, const int* __restrict__ dst, int E) {
    int w = blockIdx.x * (blockDim.x >> 5) + (threadIdx.x >> 5);
    int lane = threadIdx.x & 31;
    if (w >= E) return;
    int s = src[w];
    int d = dst[w];
    const float2* zs = (const float2*)(g_z + (long)s * F);
    const float2* zd = (const float2*)(g_z + (long)d * F);
    float2 a = zs[lane];
    float2 b = zd[lane];
    float p = a.x * b.x + a.y * b.y;
#pragma unroll
    for (int o = 16; o > 0; o >>= 1)
        p += __shfl_xor_sync(0xffffffffu, p, o);
    if (lane == 0) {
        float e = p > 0.0f ? p : 0.2f * p;
        g_ex[w] = e;
        atomicMaxFloat(&g_emax[d], e);
    }
}

// K3: ex = exp(e - emax[dst]); atomicAdd into denom[dst]
__global__ void k_exp(const int* __restrict__ dst, int E) {
    int i = blockIdx.x * blockDim.x + threadIdx.x;
    if (i >= E) return;
    int d = dst[i];
    float ex = expf(g_ex[i] - g_emax[d]);
    g_ex[i] = ex;
    atomicAdd(&g_denom[d], ex);
}

// K4: out[dst] += alpha * z[src]; alpha = ex / max(denom[dst], 1e-16)
// One warp per edge, lanes 0..15 each do a float4 RED (sm_90+ vector atomic).
__global__ void k_agg(const int* __restrict__ src, const int* __restrict__ dst,
                      float* __restrict__ out, int E) {
    int w = blockIdx.x * (blockDim.x >> 5) + (threadIdx.x >> 5);
    int lane = threadIdx.x & 31;
    if (w >= E) return;
    int s = src[w];
    int d = dst[w];
    float alpha = g_ex[w] / fmaxf(g_denom[d], 1e-16f);
    if (lane < 16) {
        const float4* zs = (const float4*)(g_z + (long)s * F);
        float4 v = zs[lane];
        v.x *= alpha; v.y *= alpha; v.z *= alpha; v.w *= alpha;
        atomicAdd(((float4*)(out + (long)d * F)) + lane, v);
    }
}

// K5: ELU in place
__global__ void k_elu(float* __restrict__ out, int N) {
    int i = blockIdx.x * blockDim.x + threadIdx.x;
    if (i >= N * F) return;
    float x = out[i];
    out[i] = x > 0.0f ? x : expm1f(x);
}

extern "C" void kernel_launch(void* const* d_in, const int* in_sizes, int n_in,
                              void* d_out, int out_size) {
    const float* d_sim = (const float*)d_in[0];
    const float* m_sim = (const float*)d_in[1];
    const float* Wd    = (const float*)d_in[2];
    const float* Wm    = (const float*)d_in[3];
    const int*   ntype = (const int*)d_in[4];
    const int*   src   = (const int*)d_in[5];
    const int*   dst   = (const int*)d_in[6];
    float* out = (float*)d_out;

    int N = in_sizes[4];
    int E = in_sizes[5];

    k_init<<<(N * F + 255) / 256, 256>>>(out, N);
    k_project<<<(N + 7) / 8, 64>>>(d_sim, m_sim, Wd, Wm, ntype, N);
    {
        int warps_per_block = 256 / 32;
        int blocks = (E + warps_per_block - 1) / warps_per_block;
        k_edge<<<blocks, 256>>>(src, dst, E);
    }
    k_exp<<<(E + 255) / 256, 256>>>(dst, E);
    {
        int warps_per_block = 256 / 32;
        int blocks = (E + warps_per_block - 1) / warps_per_block;
        k_agg<<<blocks, 256>>>(src, dst, out, E);
    }
    k_elu<<<(N * F + 255) / 256, 256>>>(out, N);
}

// round 3
// speedup vs baseline: 2.8736x; 2.8736x over previous
#include <cuda_runtime.h>
#include <math.h>

#define MAXN 50048
#define MAXE 1250048
#define F 64
#define D 256
#define SCAN_BS 1024

// Scratch (allocation-free __device__ globals)
__device__ float g_z[MAXN * F];        // projected features
__device__ int   g_cnt[MAXN];          // per-dst degree
__device__ int   g_start[MAXN];        // CSR row starts (exclusive scan)
__device__ int   g_cursor[MAXN];       // scatter cursors
__device__ int   g_csr_src[MAXE];      // src node id per CSR slot
__device__ int   g_bsum[256];          // block sums for scan

// ---------------------------------------------------------------------------
// K0: zero degree counters
__global__ void k_zero_cnt(int N) {
    int i = blockIdx.x * blockDim.x + threadIdx.x;
    if (i < N) g_cnt[i] = 0;
}

// K1: type-gated projection z = (type? d_sim : m_sim) @ (type? W_d : W_m)
// 8 nodes per block, 64 threads (one per output feature).
__global__ void k_project(const float* __restrict__ d_sim,
                          const float* __restrict__ m_sim,
                          const float* __restrict__ Wd,
                          const float* __restrict__ Wm,
                          const int* __restrict__ ntype, int N) {
    __shared__ float xs[8][D];
    __shared__ int ty[8];
    int t = threadIdx.x;            // 0..63, output feature
    int base = blockIdx.x * 8;

    if (t < 8) {
        int n = base + t;
        ty[t] = (n < N) ? ntype[n] : 0;
    }
    __syncthreads();

    for (int i = t; i < 8 * D; i += 64) {
        int r = i >> 8;
        int c = i & (D - 1);
        int n = base + r;
        if (n < N) {
            const float* p = ty[r] ? d_sim : m_sim;
            xs[r][c] = p[(long)n * D + c];
        }
    }
    __syncthreads();

    int tl[8];
#pragma unroll
    for (int m = 0; m < 8; m++) tl[m] = ty[m];

    float acc[8];
#pragma unroll
    for (int m = 0; m < 8; m++) acc[m] = 0.0f;

#pragma unroll 4
    for (int k = 0; k < D; k++) {
        float wd = __ldg(Wd + k * F + t);
        float wm = __ldg(Wm + k * F + t);
#pragma unroll
        for (int m = 0; m < 8; m++) {
            float w = tl[m] ? wd : wm;
            acc[m] = fmaf(xs[m][k], w, acc[m]);
        }
    }

#pragma unroll
    for (int m = 0; m < 8; m++) {
        int n = base + m;
        if (n < N) g_z[n * F + t] = acc[m];
    }
}

// K2: histogram of dst
__global__ void k_hist(const int* __restrict__ dst, int E) {
    int i = blockIdx.x * blockDim.x + threadIdx.x;
    if (i < E) atomicAdd(&g_cnt[dst[i]], 1);
}

// K3: per-block exclusive scan of g_cnt -> g_start (block-local), totals -> g_bsum
__global__ void k_scan_blocks(int N) {
    __shared__ int sh[SCAN_BS];
    int t = threadIdx.x;
    int i = blockIdx.x * SCAN_BS + t;
    int v = (i < N) ? g_cnt[i] : 0;
    sh[t] = v;
    __syncthreads();
#pragma unroll
    for (int o = 1; o < SCAN_BS; o <<= 1) {
        int add = (t >= o) ? sh[t - o] : 0;
        __syncthreads();
        sh[t] += add;
        __syncthreads();
    }
    if (i < N) g_start[i] = sh[t] - v;      // exclusive within block
    if (t == SCAN_BS - 1) g_bsum[blockIdx.x] = sh[t];
}

// K4: exclusive scan of block sums (tiny, single thread)
__global__ void k_scan_top(int NB) {
    if (threadIdx.x == 0 && blockIdx.x == 0) {
        int run = 0;
        for (int b = 0; b < NB; b++) {
            int v = g_bsum[b];
            g_bsum[b] = run;
            run += v;
        }
    }
}

// K5: add block offsets, init cursors
__global__ void k_add_off(int N) {
    int i = blockIdx.x * blockDim.x + threadIdx.x;
    if (i < N) {
        int s = g_start[i] + g_bsum[i / SCAN_BS];
        g_start[i] = s;
        g_cursor[i] = s;
    }
}

// K6: scatter src ids into CSR slots
__global__ void k_scatter(const int* __restrict__ src, const int* __restrict__ dst, int E) {
    int i = blockIdx.x * blockDim.x + threadIdx.x;
    if (i < E) {
        int pos = atomicAdd(&g_cursor[dst[i]], 1);
        g_csr_src[pos] = src[i];
    }
}

// K7: fused online-softmax attention aggregation + ELU.
// Half-warp (16 lanes) per dst node; each lane owns a float4 (64 features).
__global__ void k_fused(float* __restrict__ out, int N, int E) {
    int hw = blockIdx.x * (blockDim.x >> 4) + (threadIdx.x >> 4);
    int lane = threadIdx.x & 15;
    unsigned mask = 0xFFFFu << (threadIdx.x & 0x10);
    if (hw >= N) return;
    int d = hw;

    int beg = g_start[d];
    int end = (d + 1 < N) ? g_start[d + 1] : E;

    float4 zd = ((const float4*)(g_z + (long)d * F))[lane];

    float m = -INFINITY, s = 0.0f;
    float4 h = make_float4(0.f, 0.f, 0.f, 0.f);

    for (int e = beg; e < end; e++) {
        int sn = g_csr_src[e];
        float4 zs = ((const float4*)(g_z + (long)sn * F))[lane];
        float p = zs.x * zd.x + zs.y * zd.y + zs.z * zd.z + zs.w * zd.w;
        p += __shfl_xor_sync(mask, p, 1);
        p += __shfl_xor_sync(mask, p, 2);
        p += __shfl_xor_sync(mask, p, 4);
        p += __shfl_xor_sync(mask, p, 8);
        float ea = p > 0.0f ? p : 0.2f * p;          // leaky_relu
        float mn = fmaxf(m, ea);
        float c = expf(m - mn);                      // first iter: exp(-inf)=0
        float w = expf(ea - mn);
        s = s * c + w;
        h.x = h.x * c + w * zs.x;
        h.y = h.y * c + w * zs.y;
        h.z = h.z * c + w * zs.z;
        h.w = h.w * c + w * zs.w;
        m = mn;
    }

    float inv = (end > beg) ? 1.0f / fmaxf(s, 1e-16f) : 0.0f;
    float4 o;
    float x;
    x = h.x * inv; o.x = x > 0.0f ? x : expm1f(x);
    x = h.y * inv; o.y = x > 0.0f ? x : expm1f(x);
    x = h.z * inv; o.z = x > 0.0f ? x : expm1f(x);
    x = h.w * inv; o.w = x > 0.0f ? x : expm1f(x);
    ((float4*)(out + (long)d * F))[lane] = o;
}

extern "C" void kernel_launch(void* const* d_in, const int* in_sizes, int n_in,
                              void* d_out, int out_size) {
    const float* d_sim = (const float*)d_in[0];
    const float* m_sim = (const float*)d_in[1];
    const float* Wd    = (const float*)d_in[2];
    const float* Wm    = (const float*)d_in[3];
    const int*   ntype = (const int*)d_in[4];
    const int*   src   = (const int*)d_in[5];
    const int*   dst   = (const int*)d_in[6];
    float* out = (float*)d_out;

    int N = in_sizes[4];
    int E = in_sizes[5];
    int NB = (N + SCAN_BS - 1) / SCAN_BS;

    k_zero_cnt<<<(N + 255) / 256, 256>>>(N);
    k_project<<<(N + 7) / 8, 64>>>(d_sim, m_sim, Wd, Wm, ntype, N);
    k_hist<<<(E + 255) / 256, 256>>>(dst, E);
    k_scan_blocks<<<NB, SCAN_BS>>>(N);
    k_scan_top<<<1, 32>>>(NB);
    k_add_off<<<(N + 255) / 256, 256>>>(N);
    k_scatter<<<(E + 255) / 256, 256>>>(src, dst, E);
    {
        int hw_per_block = 256 / 16;
        int blocks = (N + hw_per_block - 1) / hw_per_block;
        k_fused<<<blocks, 256>>>(out, N, E);
    }
}

// round 5
// speedup vs baseline: 3.2647x; 1.1361x over previous
#include <cuda_runtime.h>
#include <math.h>

#define MAXN 50048
#define MAXE 1250048
#define F 64
#define D 256
#define SCAN_BS 1024

// Scratch (allocation-free __device__ globals)
__device__ float g_z[MAXN * F];        // projected features
__device__ int   g_cnt[MAXN];          // per-dst degree
__device__ int   g_start[MAXN];        // CSR row starts
__device__ int   g_cursor[MAXN];       // scatter cursors
__device__ int   g_csr_src[MAXE];      // src node id per CSR slot
__device__ int   g_bsum[256];          // block sums for scan
__device__ int   g_perm[MAXN];         // nodes sorted by type (type1 asc | type0 desc)
__device__ int   g_pcnt[2];            // perm cursors

// ---- f32x2 packed-FMA helpers (Blackwell FFMA2 via PTX) ----
__device__ __forceinline__ unsigned long long pack2(float lo, float hi) {
    unsigned long long r;
    asm("mov.b64 %0, {%1, %2};" : "=l"(r) : "f"(lo), "f"(hi));
    return r;
}
__device__ __forceinline__ void fma2(unsigned long long& acc,
                                     unsigned long long a, unsigned long long b) {
    asm("fma.rn.f32x2 %0, %1, %2, %0;" : "+l"(acc) : "l"(a), "l"(b));
}
__device__ __forceinline__ float lo32(unsigned long long v) {
    return __uint_as_float((unsigned)(v & 0xffffffffull));
}
__device__ __forceinline__ float hi32(unsigned long long v) {
    return __uint_as_float((unsigned)(v >> 32));
}

// K0: zero counters
__global__ void k_init(int N) {
    int i = blockIdx.x * blockDim.x + threadIdx.x;
    if (i < N) g_cnt[i] = 0;
    if (i < 2) g_pcnt[i] = 0;
}

// K1: dst histogram (i<E) + type partition perm (i<N).
__global__ void k_perm_hist(const int* __restrict__ ntype,
                            const int* __restrict__ dst, int N, int E) {
    int i = blockIdx.x * blockDim.x + threadIdx.x;
    if (i < E) atomicAdd(&g_cnt[dst[i]], 1);
    if (i < N) {
        if (ntype[i]) g_perm[atomicAdd(&g_pcnt[0], 1)] = i;
        else          g_perm[N - 1 - atomicAdd(&g_pcnt[1], 1)] = i;
    }
}

// K2: type-gated projection with f32x2 packed FMA.
// 16 nodes per block (type-homogeneous thanks to perm), 64 threads = one per feature.
// acc2 lanes hold (even-k, odd-k) partial sums; combined at the end.
__global__ void k_project(const float* __restrict__ d_sim,
                          const float* __restrict__ m_sim,
                          const float* __restrict__ Wd,
                          const float* __restrict__ Wm,
                          const int* __restrict__ ntype, int N) {
    __shared__ float xs[16][D];        // row-major, conflict-free staging
    __shared__ int ids[16];
    __shared__ int ty[16];
    int t = threadIdx.x;               // feature 0..63
    int base = blockIdx.x * 16;

    if (t < 16) {
        int slot = base + t;
        int id = (slot < N) ? g_perm[slot] : g_perm[N - 1];
        ids[t] = id;
        ty[t] = ntype[id];
    }
    __syncthreads();

    // Stage 16 rows; one full row per pass, float4 coalesced, conflict-free STS.
    for (int r = 0; r < 16; r++) {
        const float* p = ty[r] ? d_sim : m_sim;
        float4 v = ((const float4*)(p + (long)ids[r] * D))[t];
        ((float4*)xs[r])[t] = v;
    }
    __syncthreads();

    bool homo = true;
#pragma unroll
    for (int m = 1; m < 16; m++) homo &= (ty[m] == ty[0]);

    unsigned long long acc[16];
#pragma unroll
    for (int m = 0; m < 16; m++) acc[m] = 0ull;

    if (homo) {
        const float* wb = ty[0] ? Wd : Wm;
        for (int k = 0; k < D; k += 4) {
            float w0 = __ldg(wb + (k + 0) * F + t);
            float w1 = __ldg(wb + (k + 1) * F + t);
            float w2 = __ldg(wb + (k + 2) * F + t);
            float w3 = __ldg(wb + (k + 3) * F + t);
            unsigned long long w01 = pack2(w0, w1);
            unsigned long long w23 = pack2(w2, w3);
#pragma unroll
            for (int m = 0; m < 16; m++) {
                ulonglong2 x = *(const ulonglong2*)&xs[m][k];
                fma2(acc[m], x.x, w01);
                fma2(acc[m], x.y, w23);
            }
        }
    } else {
        // Rare boundary block: per-node W, same even/odd summation order.
#pragma unroll 1
        for (int m = 0; m < 16; m++) {
            const float* wb = ty[m] ? Wd : Wm;
            for (int k = 0; k < D; k += 4) {
                unsigned long long w01 = pack2(__ldg(wb + (k + 0) * F + t),
                                               __ldg(wb + (k + 1) * F + t));
                unsigned long long w23 = pack2(__ldg(wb + (k + 2) * F + t),
                                               __ldg(wb + (k + 3) * F + t));
                ulonglong2 x = *(const ulonglong2*)&xs[m][k];
                fma2(acc[m], x.x, w01);
                fma2(acc[m], x.y, w23);
            }
        }
    }

#pragma unroll
    for (int m = 0; m < 16; m++) {
        int slot = base + m;
        if (slot < N) g_z[(long)ids[m] * F + t] = lo32(acc[m]) + hi32(acc[m]);
    }
}

// K3: block-level exclusive scan (shfl), totals -> g_bsum
__global__ void k_scan_blocks(int N) {
    __shared__ int wsum[32];
    int t = threadIdx.x;
    int i = blockIdx.x * SCAN_BS + t;
    int v = (i < N) ? g_cnt[i] : 0;
    int x = v;
    int lane = t & 31, w = t >> 5;
#pragma unroll
    for (int o = 1; o < 32; o <<= 1) {
        int u = __shfl_up_sync(0xffffffffu, x, o);
        if (lane >= o) x += u;
    }
    if (lane == 31) wsum[w] = x;
    __syncthreads();
    if (w == 0) {
        int s = (lane < 32) ? wsum[lane] : 0;
#pragma unroll
        for (int o = 1; o < 32; o <<= 1) {
            int u = __shfl_up_sync(0xffffffffu, s, o);
            if (lane >= o) s += u;
        }
        wsum[lane] = s;
    }
    __syncthreads();
    int incl = x + (w > 0 ? wsum[w - 1] : 0);
    if (i < N) g_start[i] = incl - v;          // exclusive within block
    if (t == SCAN_BS - 1) g_bsum[blockIdx.x] = incl;
}

// K4: exclusive scan of <=64 block sums
__global__ void k_scan_top(int NB) {
    __shared__ int ws[2];
    int t = threadIdx.x;                       // 64 threads
    int v0 = (t < NB) ? g_bsum[t] : 0;
    int v = v0;
    int lane = t & 31, w = t >> 5;
#pragma unroll
    for (int o = 1; o < 32; o <<= 1) {
        int u = __shfl_up_sync(0xffffffffu, v, o);
        if (lane >= o) v += u;
    }
    if (lane == 31) ws[w] = v;
    __syncthreads();
    if (w == 1) v += ws[0];
    if (t < NB) g_bsum[t] = v - v0;            // exclusive
}

// K5: add block offsets, init cursors
__global__ void k_add_off(int N) {
    int i = blockIdx.x * blockDim.x + threadIdx.x;
    if (i < N) {
        int s = g_start[i] + g_bsum[i / SCAN_BS];
        g_start[i] = s;
        g_cursor[i] = s;
    }
}

// K6: scatter src ids into CSR slots
__global__ void k_scatter(const int* __restrict__ src, const int* __restrict__ dst, int E) {
    int i = blockIdx.x * blockDim.x + threadIdx.x;
    if (i < E) {
        int pos = atomicAdd(&g_cursor[dst[i]], 1);
        g_csr_src[pos] = src[i];
    }
}

// K7: fused online-softmax aggregation + ELU.
// Half-warp per dst node; single __expf per edge; prefetch-pipelined gather.
__global__ void k_fused(float* __restrict__ out, int N, int E) {
    int hw = blockIdx.x * (blockDim.x >> 4) + (threadIdx.x >> 4);
    int lane = threadIdx.x & 15;
    unsigned mask = 0xFFFFu << (threadIdx.x & 0x10);
    if (hw >= N) return;
    int d = hw;

    int beg = g_start[d];
    int end = (d + 1 < N) ? g_start[d + 1] : E;

    if (beg == end) {
        ((float4*)(out + (long)d * F))[lane] = make_float4(0.f, 0.f, 0.f, 0.f);
        return;
    }

    float4 zd = __ldg(((const float4*)(g_z + (long)d * F)) + lane);

    float m = -INFINITY, s = 0.0f;
    float4 h = make_float4(0.f, 0.f, 0.f, 0.f);

    int sn = __ldg(g_csr_src + beg);
    float4 zs = __ldg(((const float4*)(g_z + (long)sn * F)) + lane);

    for (int e = beg; e < end; e++) {
        float4 cur = zs;
        if (e + 1 < end) {
            int sn2 = __ldg(g_csr_src + e + 1);
            zs = __ldg(((const float4*)(g_z + (long)sn2 * F)) + lane);
        }
        float p = cur.x * zd.x + cur.y * zd.y + cur.z * zd.z + cur.w * zd.w;
        p += __shfl_xor_sync(mask, p, 1);
        p += __shfl_xor_sync(mask, p, 2);
        p += __shfl_xor_sync(mask, p, 4);
        p += __shfl_xor_sync(mask, p, 8);
        float ea = p > 0.0f ? p : 0.2f * p;          // leaky_relu
        if (ea <= m) {
            float w = __expf(ea - m);
            s += w;
            h.x = fmaf(w, cur.x, h.x);
            h.y = fmaf(w, cur.y, h.y);
            h.z = fmaf(w, cur.z, h.z);
            h.w = fmaf(w, cur.w, h.w);
        } else {
            float c = __expf(m - ea);                // first iter: exp(-inf)=0
            s = fmaf(s, c, 1.0f);
            h.x = fmaf(h.x, c, cur.x);
            h.y = fmaf(h.y, c, cur.y);
            h.z = fmaf(h.z, c, cur.z);
            h.w = fmaf(h.w, c, cur.w);
            m = ea;
        }
    }

    float inv = 1.0f / s;                            // s >= 1 (max term)
    float4 o;
    float x;
    x = h.x * inv; o.x = x > 0.0f ? x : expm1f(x);
    x = h.y * inv; o.y = x > 0.0f ? x : expm1f(x);
    x = h.z * inv; o.z = x > 0.0f ? x : expm1f(x);
    x = h.w * inv; o.w = x > 0.0f ? x : expm1f(x);
    ((float4*)(out + (long)d * F))[lane] = o;
}

extern "C" void kernel_launch(void* const* d_in, const int* in_sizes, int n_in,
                              void* d_out, int out_size) {
    const float* d_sim = (const float*)d_in[0];
    const float* m_sim = (const float*)d_in[1];
    const float* Wd    = (const float*)d_in[2];
    const float* Wm    = (const float*)d_in[3];
    const int*   ntype = (const int*)d_in[4];
    const int*   src   = (const int*)d_in[5];
    const int*   dst   = (const int*)d_in[6];
    float* out = (float*)d_out;

    int N = in_sizes[4];
    int E = in_sizes[5];
    int NB = (N + SCAN_BS - 1) / SCAN_BS;

    k_init<<<(N + 255) / 256, 256>>>(N);
    k_perm_hist<<<(max(N, E) + 255) / 256, 256>>>(ntype, dst, N, E);
    k_project<<<(N + 15) / 16, 64>>>(d_sim, m_sim, Wd, Wm, ntype, N);
    k_scan_blocks<<<NB, SCAN_BS>>>(N);
    k_scan_top<<<1, 64>>>(NB);
    k_add_off<<<(N + 255) / 256, 256>>>(N);
    k_scatter<<<(E + 255) / 256, 256>>>(src, dst, E);
    {
        int hw_per_block = 256 / 16;
        int blocks = (N + hw_per_block - 1) / hw_per_block;
        k_fused<<<blocks, 256>>>(out, N, E);
    }
}

// round 9
// speedup vs baseline: 3.2770x; 1.0038x over previous
#include <cuda_runtime.h>
#include <math.h>

#define MAXN 50048
#define MAXE 1250048
#define F 64
#define D 256
#define SCAN_BS 1024
#define HB_BLOCKS 2048
#define SB_BLOCKS 2048

// Scratch (allocation-free __device__ globals)
__device__ float g_z[MAXN * F];
__device__ int   g_cnt[MAXN];
__device__ int   g_start[MAXN];
__device__ int   g_cursor[MAXN];
__device__ int   g_csr_src[MAXE];
__device__ int   g_bsum[256];
__device__ int   g_perm[MAXN];         // nodes partitioned by type
__device__ int   g_pcnt[2];

// ---- f32x2 packed-FMA helpers (Blackwell FFMA2 via PTX) ----
__device__ __forceinline__ unsigned long long pack2(float lo, float hi) {
    unsigned long long r;
    asm("mov.b64 %0, {%1, %2};" : "=l"(r) : "f"(lo), "f"(hi));
    return r;
}
__device__ __forceinline__ void fma2(unsigned long long& acc,
                                     unsigned long long a, unsigned long long b) {
    asm("fma.rn.f32x2 %0, %1, %2, %0;" : "+l"(acc) : "l"(a), "l"(b));
}
__device__ __forceinline__ float lo32(unsigned long long v) {
    return __uint_as_float((unsigned)(v & 0xffffffffull));
}
__device__ __forceinline__ float hi32(unsigned long long v) {
    return __uint_as_float((unsigned)(v >> 32));
}

// K0: zero counters
__global__ void k_init(int N) {
    int i = blockIdx.x * blockDim.x + threadIdx.x;
    if (i < N) g_cnt[i] = 0;
    if (i < 2) g_pcnt[i] = 0;
}

// K1: type partition perm (type1 front, type0 back)
__global__ void k_perm(const int* __restrict__ ntype, int N) {
    int i = blockIdx.x * blockDim.x + threadIdx.x;
    if (i < N) {
        if (ntype[i]) g_perm[atomicAdd(&g_pcnt[0], 1)] = i;
        else          g_perm[N - 1 - atomicAdd(&g_pcnt[1], 1)] = i;
    }
}

// Projection block body: 16 perm-slots starting at slot_base, 64 threads.
__device__ __forceinline__ void proj_block(const float* __restrict__ d_sim,
                                           const float* __restrict__ m_sim,
                                           const float* __restrict__ Wd,
                                           const float* __restrict__ Wm,
                                           const int* __restrict__ ntype,
                                           int N, int slot_base,
                                           float (*xs)[D], int* ids, int* ty) {
    int t = threadIdx.x;               // feature 0..63

    if (t < 16) {
        int slot = slot_base + t;
        int id = (slot < N) ? g_perm[slot] : g_perm[N - 1];
        ids[t] = id;
        ty[t] = ntype[id];
    }
    __syncthreads();

    for (int r = 0; r < 16; r++) {
        const float* p = ty[r] ? d_sim : m_sim;
        float4 v = ((const float4*)(p + (long)ids[r] * D))[t];
        ((float4*)xs[r])[t] = v;
    }
    __syncthreads();

    bool homo = true;
#pragma unroll
    for (int m = 1; m < 16; m++) homo &= (ty[m] == ty[0]);

    unsigned long long acc[16];
#pragma unroll
    for (int m = 0; m < 16; m++) acc[m] = 0ull;

    if (homo) {
        const float* wb = ty[0] ? Wd : Wm;
        for (int k = 0; k < D; k += 4) {
            float w0 = __ldg(wb + (k + 0) * F + t);
            float w1 = __ldg(wb + (k + 1) * F + t);
            float w2 = __ldg(wb + (k + 2) * F + t);
            float w3 = __ldg(wb + (k + 3) * F + t);
            unsigned long long w01 = pack2(w0, w1);
            unsigned long long w23 = pack2(w2, w3);
#pragma unroll
            for (int m = 0; m < 16; m++) {
                ulonglong2 x = *(const ulonglong2*)&xs[m][k];
                fma2(acc[m], x.x, w01);
                fma2(acc[m], x.y, w23);
            }
        }
    } else {
#pragma unroll 1
        for (int m = 0; m < 16; m++) {
            const float* wb = ty[m] ? Wd : Wm;
            for (int k = 0; k < D; k += 4) {
                unsigned long long w01 = pack2(__ldg(wb + (k + 0) * F + t),
                                               __ldg(wb + (k + 1) * F + t));
                unsigned long long w23 = pack2(__ldg(wb + (k + 2) * F + t),
                                               __ldg(wb + (k + 3) * F + t));
                ulonglong2 x = *(const ulonglong2*)&xs[m][k];
                fma2(acc[m], x.x, w01);
                fma2(acc[m], x.y, w23);
            }
        }
    }

#pragma unroll
    for (int m = 0; m < 16; m++) {
        int slot = slot_base + m;
        if (slot < N) g_z[(long)ids[m] * F + t] = lo32(acc[m]) + hi32(acc[m]);
    }
}

// M1: projection part A (blocks [0, PA)) ∥ dst histogram (blocks [PA, PA+HB))
__global__ void k_m1(const float* __restrict__ d_sim, const float* __restrict__ m_sim,
                     const float* __restrict__ Wd, const float* __restrict__ Wm,
                     const int* __restrict__ ntype, const int* __restrict__ dst,
                     int N, int E, int PA) {
    __shared__ float xs[16][D];
    __shared__ int ids[16];
    __shared__ int ty[16];
    int bid = blockIdx.x;
    if (bid < PA) {
        proj_block(d_sim, m_sim, Wd, Wm, ntype, N, bid * 16, xs, ids, ty);
    } else {
        int i = (bid - PA) * 64 + threadIdx.x;
        int stride = HB_BLOCKS * 64;
        for (; i < E; i += stride)
            atomicAdd(&g_cnt[dst[i]], 1);
    }
}

// M2: projection part B (blocks [0, PB)) ∥ CSR scatter (blocks [PB, PB+SB))
__global__ void k_m2(const float* __restrict__ d_sim, const float* __restrict__ m_sim,
                     const float* __restrict__ Wd, const float* __restrict__ Wm,
                     const int* __restrict__ ntype,
                     const int* __restrict__ src, const int* __restrict__ dst,
                     int N, int E, int NA, int PB) {
    __shared__ float xs[16][D];
    __shared__ int ids[16];
    __shared__ int ty[16];
    int bid = blockIdx.x;
    if (bid < PB) {
        proj_block(d_sim, m_sim, Wd, Wm, ntype, N, NA + bid * 16, xs, ids, ty);
    } else {
        int i = (bid - PB) * 64 + threadIdx.x;
        int stride = SB_BLOCKS * 64;
        for (; i < E; i += stride) {
            int pos = atomicAdd(&g_cursor[dst[i]], 1);
            g_csr_src[pos] = src[i];
        }
    }
}

// Scan: block-level exclusive scan (shfl), totals -> g_bsum
__global__ void k_scan_blocks(int N) {
    __shared__ int wsum[32];
    int t = threadIdx.x;
    int i = blockIdx.x * SCAN_BS + t;
    int v = (i < N) ? g_cnt[i] : 0;
    int x = v;
    int lane = t & 31, w = t >> 5;
#pragma unroll
    for (int o = 1; o < 32; o <<= 1) {
        int u = __shfl_up_sync(0xffffffffu, x, o);
        if (lane >= o) x += u;
    }
    if (lane == 31) wsum[w] = x;
    __syncthreads();
    if (w == 0) {
        int s = (lane < 32) ? wsum[lane] : 0;
#pragma unroll
        for (int o = 1; o < 32; o <<= 1) {
            int u = __shfl_up_sync(0xffffffffu, s, o);
            if (lane >= o) s += u;
        }
        wsum[lane] = s;
    }
    __syncthreads();
    int incl = x + (w > 0 ? wsum[w - 1] : 0);
    if (i < N) g_start[i] = incl - v;
    if (t == SCAN_BS - 1) g_bsum[blockIdx.x] = incl;
}

__global__ void k_scan_top(int NB) {
    __shared__ int ws[2];
    int t = threadIdx.x;                       // 64 threads
    int v0 = (t < NB) ? g_bsum[t] : 0;
    int v = v0;
    int lane = t & 31, w = t >> 5;
#pragma unroll
    for (int o = 1; o < 32; o <<= 1) {
        int u = __shfl_up_sync(0xffffffffu, v, o);
        if (lane >= o) v += u;
    }
    if (lane == 31) ws[w] = v;
    __syncthreads();
    if (w == 1) v += ws[0];
    if (t < NB) g_bsum[t] = v - v0;
}

__global__ void k_add_off(int N) {
    int i = blockIdx.x * blockDim.x + threadIdx.x;
    if (i < N) {
        int s = g_start[i] + g_bsum[i / SCAN_BS];
        g_start[i] = s;
        g_cursor[i] = s;
    }
}

// Fused online-softmax aggregation + ELU. Half-warp per dst node.
__global__ void k_fused(float* __restrict__ out, int N, int E) {
    int hw = blockIdx.x * (blockDim.x >> 4) + (threadIdx.x >> 4);
    int lane = threadIdx.x & 15;
    unsigned mask = 0xFFFFu << (threadIdx.x & 0x10);
    if (hw >= N) return;
    int d = hw;

    int beg = g_start[d];
    int end = (d + 1 < N) ? g_start[d + 1] : E;

    if (beg == end) {
        ((float4*)(out + (long)d * F))[lane] = make_float4(0.f, 0.f, 0.f, 0.f);
        return;
    }

    float4 zd = __ldg(((const float4*)(g_z + (long)d * F)) + lane);

    float m = -INFINITY, s = 0.0f;
    float4 h = make_float4(0.f, 0.f, 0.f, 0.f);

    // 2-deep pipeline: idx 2-ahead, row 1-ahead
    int i0 = __ldg(g_csr_src + beg);
    float4 zs = __ldg(((const float4*)(g_z + (long)i0 * F)) + lane);
    int i1 = (beg + 1 < end) ? __ldg(g_csr_src + beg + 1) : 0;

    for (int e = beg; e < end; e++) {
        float4 cur = zs;
        if (e + 1 < end)
            zs = __ldg(((const float4*)(g_z + (long)i1 * F)) + lane);
        if (e + 2 < end)
            i1 = __ldg(g_csr_src + e + 2);

        float p = cur.x * zd.x + cur.y * zd.y + cur.z * zd.z + cur.w * zd.w;
        p += __shfl_xor_sync(mask, p, 1);
        p += __shfl_xor_sync(mask, p, 2);
        p += __shfl_xor_sync(mask, p, 4);
        p += __shfl_xor_sync(mask, p, 8);
        float ea = p > 0.0f ? p : 0.2f * p;          // leaky_relu
        if (ea <= m) {
            float w = __expf(ea - m);
            s += w;
            h.x = fmaf(w, cur.x, h.x);
            h.y = fmaf(w, cur.y, h.y);
            h.z = fmaf(w, cur.z, h.z);
            h.w = fmaf(w, cur.w, h.w);
        } else {
            float c = __expf(m - ea);                // first iter: exp(-inf)=0
            s = fmaf(s, c, 1.0f);
            h.x = fmaf(h.x, c, cur.x);
            h.y = fmaf(h.y, c, cur.y);
            h.z = fmaf(h.z, c, cur.z);
            h.w = fmaf(h.w, c, cur.w);
            m = ea;
        }
    }

    float inv = 1.0f / s;                            // s >= 1 (max term)
    float4 o;
    float x;
    x = h.x * inv; o.x = x > 0.0f ? x : expm1f(x);
    x = h.y * inv; o.y = x > 0.0f ? x : expm1f(x);
    x = h.z * inv; o.z = x > 0.0f ? x : expm1f(x);
    x = h.w * inv; o.w = x > 0.0f ? x : expm1f(x);
    ((float4*)(out + (long)d * F))[lane] = o;
}

extern "C" void kernel_launch(void* const* d_in, const int* in_sizes, int n_in,
                              void* d_out, int out_size) {
    const float* d_sim = (const float*)d_in[0];
    const float* m_sim = (const float*)d_in[1];
    const float* Wd    = (const float*)d_in[2];
    const float* Wm    = (const float*)d_in[3];
    const int*   ntype = (const int*)d_in[4];
    const int*   src   = (const int*)d_in[5];
    const int*   dst   = (const int*)d_in[6];
    float* out = (float*)d_out;

    int N = in_sizes[4];
    int E = in_sizes[5];
    int NB = (N + SCAN_BS - 1) / SCAN_BS;

    int NA = ((N / 2) / 16) * 16;                 // proj split point (multiple of 16)
    int PA = (NA + 15) / 16;                      // proj blocks in M1
    int PB = (N - NA + 15) / 16;                  // proj blocks in M2

    k_init<<<(N + 255) / 256, 256>>>(N);
    k_perm<<<(N + 255) / 256, 256>>>(ntype, N);
    k_m1<<<PA + HB_BLOCKS, 64>>>(d_sim, m_sim, Wd, Wm, ntype, dst, N, E, PA);
    k_scan_blocks<<<NB, SCAN_BS>>>(N);
    k_scan_top<<<1, 64>>>(NB);
    k_add_off<<<(N + 255) / 256, 256>>>(N);
    k_m2<<<PB + SB_BLOCKS, 64>>>(d_sim, m_sim, Wd, Wm, ntype, src, dst, N, E, NA, PB);
    {
        int hw_per_block = 256 / 16;
        int blocks = (N + hw_per_block - 1) / hw_per_block;
        k_fused<<<blocks, 256>>>(out, N, E);
    }
}